// round 13
// baseline (speedup 1.0000x reference)
#include <cuda_runtime.h>
#include <cstdint>

// ---------------- problem constants ----------------
#define N_NODES 4096
#define UNITS   64
#define BATCH   32
#define TSTEPS  12
#define PRELEN  12
#define NC      2048                 // GEMM columns for state (b*64+u)
#define TB      384                  // t*32+b columns for X
#define A_PART  ((size_t)N_NODES * N_NODES)
#define ROWB    80u                  // smem row stride: 64B data + 16B pad
#define KHALF   (N_NODES/128)        // 32 k-tiles of BK=64 per K-half

// ---------------- scratch (device globals; no allocation allowed) ----------------
__device__ __align__(128) float g_S  [N_NODES*NC];  // state fp32 [node][col]
__device__ __align__(128) float g_AS [N_NODES*NC];  // GEMM half-0 output
__device__ __align__(128) float g_AR [N_NODES*NC];  // GEMM half-1 output
__device__ __align__(128) float g_RS [N_NODES*NC];  // r * state
__device__ __align__(128) float g_UG [N_NODES*NC];  // u gate
__device__ __align__(128) float g_AX [N_NODES*TB];  // A @ X half-0
__device__ __align__(128) float g_AX2[N_NODES*TB];  // A @ X half-1
__device__ __align__(128) char g_Aq[2*A_PART];                // A planes: a1 | a0, [m][k]
__device__ __align__(128) char g_Sq[2*(size_t)NC*N_NODES];    // S planes: b1 | b0, [n][k]
__device__ __align__(128) char g_Rq[2*(size_t)NC*N_NODES];    // RS planes
__device__ __align__(128) char g_Xq[2*(size_t)TB*N_NODES];    // X planes

// ---------------- PTX helpers (baseline PTX, sm_80+) ----------------
__device__ __forceinline__ uint32_t s2u(const void* p) {
    uint32_t a;
    asm("{ .reg .u64 t; cvta.to.shared.u64 t, %1; cvt.u32.u64 %0, t; }" : "=r"(a) : "l"(p));
    return a;
}
__device__ __forceinline__ void cp16(uint32_t dst, const void* src) {
    asm volatile("cp.async.cg.shared.global [%0], [%1], 16;" :: "r"(dst), "l"(src) : "memory");
}
__device__ __forceinline__ void cp_commit() {
    asm volatile("cp.async.commit_group;" ::: "memory");
}
template<int N>
__device__ __forceinline__ void cp_wait() {
    asm volatile("cp.async.wait_group %0;" :: "n"(N) : "memory");
}
__device__ __forceinline__ void ldm_x4(uint32_t* r, uint32_t a) {
    asm volatile("ldmatrix.sync.aligned.m8n8.x4.shared.b16 {%0,%1,%2,%3}, [%4];"
                 : "=r"(r[0]), "=r"(r[1]), "=r"(r[2]), "=r"(r[3]) : "r"(a));
}
// int8 IMMA m16n8k32, s32 accum
__device__ __forceinline__ void imma_u8s8(int* d, const uint32_t* a, const uint32_t* b) {
    asm volatile(
        "mma.sync.aligned.m16n8k32.row.col.s32.u8.s8.s32 "
        "{%0,%1,%2,%3}, {%4,%5,%6,%7}, {%8,%9}, {%0,%1,%2,%3};"
        : "+r"(d[0]), "+r"(d[1]), "+r"(d[2]), "+r"(d[3])
        : "r"(a[0]), "r"(a[1]), "r"(a[2]), "r"(a[3]), "r"(b[0]), "r"(b[1]));
}
__device__ __forceinline__ void imma_s8s8(int* d, const uint32_t* a, const uint32_t* b) {
    asm volatile(
        "mma.sync.aligned.m16n8k32.row.col.s32.s8.s8.s32 "
        "{%0,%1,%2,%3}, {%4,%5,%6,%7}, {%8,%9}, {%0,%1,%2,%3};"
        : "+r"(d[0]), "+r"(d[1]), "+r"(d[2]), "+r"(d[3])
        : "r"(a[0]), "r"(a[1]), "r"(a[2]), "r"(a[3]), "r"(b[0]), "r"(b[1]));
}
// packed fp32x2 FMA (Blackwell FFMA2)
__device__ __forceinline__ void ffma2(unsigned long long &d,
                                      unsigned long long a,
                                      unsigned long long b) {
    asm("fma.rn.f32x2 %0, %1, %2, %0;" : "+l"(d) : "l"(a), "l"(b));
}
__device__ __forceinline__ unsigned long long pk2(float x, float y) {
    unsigned long long r;
    asm("mov.b64 %0, {%1, %2};" : "=l"(r)
        : "r"(__float_as_uint(x)), "r"(__float_as_uint(y)));
    return r;
}
__device__ __forceinline__ float2 unpk(unsigned long long v) {
    unsigned int lo, hi;
    asm("mov.b64 {%0, %1}, %2;" : "=r"(lo), "=r"(hi) : "l"(v));
    return make_float2(__uint_as_float(lo), __uint_as_float(hi));
}

// ---------------- IMMA fixed-point split-GEMM, K-split 2 ----------------
// C[m,n] = sum_k A[m,k]*B[n,k]; A = (a1*256 + a0)*2^-26, B = (b1*256 + b0)*2^-12.
// C = (acc_hh*65536 + acc_x*256)*2^-38 (dropped a0*b0: centered, zero-mean).
// blockIdx.z in {0,1} selects K half and output buffer (C0 / C1); the consumer
// sums the two buffers. CTA tile 128x64, 256 threads (2 CTAs/SM),
// warp grid 4m x 2n, warp tile 32x32, BK=64, 3-stage cp.async pipeline.
#define A0_OFF 10240u
#define B1_OFF 20480u
#define B0_OFF 25600u
#define STGB   30720u

__global__ __launch_bounds__(256, 2)
void imma_gemm(float* __restrict__ C0, float* __restrict__ C1,
               const char* __restrict__ Aq, const char* __restrict__ Bq,
               int ncols, size_t bPart) {
    extern __shared__ __align__(128) char smem[];
    const uint32_t sm0 = s2u(smem);

    const int tid = threadIdx.x;
    const int lane = tid & 31, wid = tid >> 5;
    const int wm = wid & 3, wn = wid >> 2;          // 4m x 2n warps, 32x32 tiles
    const int m0 = blockIdx.y * 128;
    const int n0 = blockIdx.x * 64;
    const int kBase = blockIdx.z * (N_NODES / 2);
    float* __restrict__ C = blockIdx.z ? C1 : C0;

    int acc_hh[2][4][4], acc_x[2][4][4];
#pragma unroll
    for (int i = 0; i < 2; ++i)
#pragma unroll
        for (int j = 0; j < 4; ++j)
#pragma unroll
            for (int q = 0; q < 4; ++q) { acc_hh[i][j][q] = 0; acc_x[i][j][q] = 0; }

    auto load_stage = [&](int kt) {
        const uint32_t sb = sm0 + (uint32_t)(kt % 3) * STGB;
        const size_t k0 = (size_t)kBase + (size_t)kt * 64;
#pragma unroll
        for (int it = 0; it < 6; ++it) {
            const int i = tid + it * 256;           // 0..1535 16B chunks
            const int chunk = i & 3;                // 4 chunks = 64B row
            const int row = i >> 2;                 // 0..383
            const char* src;
            uint32_t rel;
            if (row < 256) {                        // A planes: a1 rows 0-127, a0 128-255
                const int plane = row >> 7, m = row & 127;
                src = Aq + (size_t)plane * A_PART + (size_t)(m0 + m) * N_NODES + k0;
                rel = (uint32_t)plane * A0_OFF + (uint32_t)m * ROWB;
            } else {                                // B planes: b1 rows 256-319, b0 320-383
                const int r = row - 256;
                const int plane = r >> 6, n = r & 63;
                src = Bq + (size_t)plane * bPart + (size_t)(n0 + n) * N_NODES + k0;
                rel = B1_OFF + (uint32_t)plane * (B0_OFF - B1_OFF) + (uint32_t)n * ROWB;
            }
            cp16(sb + rel + (uint32_t)chunk * 16u, src + chunk * 16);
        }
        cp_commit();
    };

    load_stage(0);
    load_stage(1);

    const uint32_t aLane = (uint32_t)(lane & 15) * ROWB + (uint32_t)((lane >> 4) << 4);
    const uint32_t bLane = (uint32_t)(((lane >> 4) << 3) + (lane & 7)) * ROWB
                         + (uint32_t)(((lane >> 3) & 1) << 4);

#pragma unroll 1
    for (int kt = 0; kt < KHALF; ++kt) {
        if (kt < KHALF - 1) cp_wait<1>();
        else                cp_wait<0>();
        __syncthreads();
        if (kt + 2 < KHALF) load_stage(kt + 2);

        const uint32_t sb = sm0 + (uint32_t)(kt % 3) * STGB;
        const uint32_t aBase1 = sb + (uint32_t)(wm * 32) * ROWB + aLane;
        const uint32_t bBase1 = sb + B1_OFF + (uint32_t)(wn * 32) * ROWB + bLane;

#pragma unroll
        for (int ks = 0; ks < 2; ++ks) {
            const uint32_t kb = (uint32_t)(ks * 32);        // 32 int8 = 32B
            uint32_t fb1[4][2], fb0[4][2];
#pragma unroll
            for (int nf2 = 0; nf2 < 2; ++nf2) {
                const uint32_t off = (uint32_t)(nf2 * 16) * ROWB + kb;
                uint32_t t1[4], t0[4];
                ldm_x4(t1, bBase1 + off);
                ldm_x4(t0, bBase1 + off + (B0_OFF - B1_OFF));
                fb1[2 * nf2][0] = t1[0]; fb1[2 * nf2][1] = t1[1];
                fb1[2 * nf2 + 1][0] = t1[2]; fb1[2 * nf2 + 1][1] = t1[3];
                fb0[2 * nf2][0] = t0[0]; fb0[2 * nf2][1] = t0[1];
                fb0[2 * nf2 + 1][0] = t0[2]; fb0[2 * nf2 + 1][1] = t0[3];
            }
#pragma unroll
            for (int mf = 0; mf < 2; ++mf) {
                const uint32_t aa = aBase1 + (uint32_t)(mf * 16) * ROWB + kb;
                uint32_t fa1[4], fa0[4];
                ldm_x4(fa1, aa);
                ldm_x4(fa0, aa + A0_OFF);
#pragma unroll
                for (int nf = 0; nf < 4; ++nf) imma_u8s8(acc_hh[mf][nf], fa1, fb1[nf]);
#pragma unroll
                for (int nf = 0; nf < 4; ++nf) imma_u8s8(acc_x[mf][nf], fa1, fb0[nf]);
#pragma unroll
                for (int nf = 0; nf < 4; ++nf) imma_s8s8(acc_x[mf][nf], fa0, fb1[nf]);
            }
        }
    }

    // epilogue: C = (hh*2^16 + cross*2^8) * 2^-38
    const float SC = 3.637978807091713e-12f;   // 2^-38
    const int grp = lane >> 2, tl = lane & 3;
#pragma unroll
    for (int mf = 0; mf < 2; ++mf) {
#pragma unroll
        for (int nf = 0; nf < 4; ++nf) {
            const int row = m0 + wm * 32 + mf * 16 + grp;
            const int col = n0 + wn * 32 + nf * 8 + tl * 2;
            float* p0 = C + (size_t)row * ncols + col;
            float* p1 = C + (size_t)(row + 8) * ncols + col;
            p0[0] = ((float)acc_hh[mf][nf][0] * 65536.f + (float)acc_x[mf][nf][0] * 256.f) * SC;
            p0[1] = ((float)acc_hh[mf][nf][1] * 65536.f + (float)acc_x[mf][nf][1] * 256.f) * SC;
            p1[0] = ((float)acc_hh[mf][nf][2] * 65536.f + (float)acc_x[mf][nf][2] * 256.f) * SC;
            p1[1] = ((float)acc_hh[mf][nf][3] * 65536.f + (float)acc_x[mf][nf][3] * 256.f) * SC;
        }
    }
}

// ---------------- quantize A (once): A in [0, 2^-12) -> 16-bit fixed, planes a1|a0 ----------------
__global__ void quantA_kernel(const float* __restrict__ in) {
    int i = blockIdx.x * blockDim.x + threadIdx.x;
    if (i < N_NODES * N_NODES) {
        int q = (int)rintf(in[i] * 67108864.f);    // 2^26, <= 16384
        int h = (q + 128) >> 8;                     // [0,64]
        g_Aq[i] = (char)h;
        g_Aq[A_PART + i] = (char)(q - (h << 8));    // [-128,127]
    }
}

// ---------------- quantize B helper ----------------
__device__ __forceinline__ void quantB(float v, char& b1, char& b0) {
    v = fminf(fmaxf(v, -7.93f), 7.93f);
    int q = (int)rintf(v * 4096.f);                 // 2^12, |q| <= 32481
    int h = (q + 128) >> 8;                          // [-126,127]
    b1 = (char)h;
    b0 = (char)(q - (h << 8));                       // [-128,127]
}

// ---------------- quantize X (already [tb][node] k-contiguous) ----------------
__global__ void quantX_kernel(const float* __restrict__ X) {
    int i = blockIdx.x * blockDim.x + threadIdx.x;
    if (i < TB * N_NODES) {
        char b1, b0;
        quantB(X[i], b1, b0);
        g_Xq[i] = b1;
        g_Xq[(size_t)TB * N_NODES + i] = b0;
    }
}

// ---------------- transpose + quantize: fp32 [node][col] -> int8 planes [col][node] ----------------
__global__ __launch_bounds__(256)
void quantT_kernel(const float* __restrict__ in, char* __restrict__ out) {
    __shared__ float tile[32][33];
    const int col0 = blockIdx.x * 32, node0 = blockIdx.y * 32;
    const int tx = threadIdx.x, ty = threadIdx.y;
#pragma unroll
    for (int j = 0; j < 32; j += 8)
        tile[ty + j][tx] = in[(size_t)(node0 + ty + j) * NC + col0 + tx];
    __syncthreads();
#pragma unroll
    for (int j = 0; j < 32; j += 8) {
        char b1, b0;
        quantB(tile[tx][ty + j], b1, b0);
        size_t o = (size_t)(col0 + ty + j) * N_NODES + node0 + tx;
        out[o] = b1;
        out[(size_t)NC * N_NODES + o] = b0;
    }
}

// ---------------- input packing: state -> [node][col] fp32 ----------------
__global__ void pack_s_kernel(const float* __restrict__ st) {
    int i = blockIdx.x * blockDim.x + threadIdx.x;  // over B*N*U
    if (i < BATCH * N_NODES * UNITS) {
        int u = i & 63;
        int n = (i >> 6) & (N_NODES - 1);
        int b = i >> 18;
        g_S[n * NC + b * UNITS + u] = st[i];
    }
}

// ---------------- gate 1: v1 = sigmoid(gc1); scatter r*state -> RS, u -> UG ----------------
// Reads AS = g_AS + g_AR (K-split halves), AX = g_AX + g_AX2.
// TGCN chunk(2,dim=1) quirk on flattened (N,2U):
//   v1[b,n,j] is r for node 2n+(j>>6), unit j&63   when n < 2048
//   v1[b,n,j] is u for node 2(n-2048)+(j>>6)       when n >= 2048
__global__ __launch_bounds__(128)
void gates1_kernel(const float* __restrict__ W1, const float* __restrict__ b1, int t) {
    __shared__ __align__(16) float asr[16][64];
    __shared__ float axs[16];
    const int j  = threadIdx.x;          // 0..127 output feature
    const int n  = blockIdx.y;           // v1 node
    const int b0 = blockIdx.x * 16;      // batch block
    const float w0 = W1[j];
    unsigned long long wp[32];           // pairs (w[2q+1], w[2q+2])
#pragma unroll
    for (int q = 0; q < 32; ++q)
        wp[q] = pk2(W1[(2 * q + 1) * 128 + j], W1[(2 * q + 2) * 128 + j]);
    const float bias = b1[j];

    const float* srcA = g_AS + n * NC + b0 * UNITS;
    const float* srcB = g_AR + n * NC + b0 * UNITS;
    for (int idx = j; idx < 1024; idx += 128) ((float*)asr)[idx] = srcA[idx] + srcB[idx];
    if (j < 16) {
        const int o = n * TB + t * BATCH + b0 + j;
        axs[j] = g_AX[o] + g_AX2[o];
    }
    __syncthreads();

    const int jh = j >> 6, u2 = j & 63;
    for (int p = 0; p < 16; ++p) {
        unsigned long long acc2a = 0ull, acc2b = 0ull;
        const ulonglong2* ap = (const ulonglong2*)asr[p];
#pragma unroll
        for (int q = 0; q < 16; ++q) {
            ulonglong2 v = ap[q];
            ffma2(acc2a, v.x, wp[2 * q]);
            ffma2(acc2b, v.y, wp[2 * q + 1]);
        }
        float2 sa = unpk(acc2a), sb = unpk(acc2b);
        float acc = bias + axs[p] * w0 + (sa.x + sa.y) + (sb.x + sb.y);
        float sg = 1.f / (1.f + __expf(-acc));
        const int b = b0 + p;
        if (n < 2048) {
            const int idx = (2 * n + jh) * NC + b * UNITS + u2;
            g_RS[idx] = sg * g_S[idx];
        } else {
            g_UG[(2 * (n - 2048) + jh) * NC + b * UNITS + u2] = sg;
        }
    }
}

// ---------------- gate 2: c = tanh(gc2); state = u*state + (1-u)*c ----------------
// Reads AR = g_AS + g_AR (K-split halves), AX = g_AX + g_AX2.
__global__ __launch_bounds__(128)
void gates2_kernel(const float* __restrict__ W2, const float* __restrict__ b2, int t) {
    __shared__ __align__(16) float arr[16][64];
    __shared__ float axs[16];
    const int j  = threadIdx.x;
    const int n  = blockIdx.y;           // real node
    const int b0 = blockIdx.x * 16;
    const int u2 = j & 63, ph = j >> 6;
    const float w0 = W2[u2];
    unsigned long long wp[32];           // pairs (w[2q+1], w[2q+2])
#pragma unroll
    for (int q = 0; q < 32; ++q)
        wp[q] = pk2(W2[(2 * q + 1) * 64 + u2], W2[(2 * q + 2) * 64 + u2]);
    const float bias = b2[u2];

    const float* srcA = g_AS + n * NC + b0 * UNITS;
    const float* srcB = g_AR + n * NC + b0 * UNITS;
    for (int idx = j; idx < 1024; idx += 128) ((float*)arr)[idx] = srcA[idx] + srcB[idx];
    if (j < 16) {
        const int o = n * TB + t * BATCH + b0 + j;
        axs[j] = g_AX[o] + g_AX2[o];
    }
    __syncthreads();

    for (int pp = 0; pp < 8; ++pp) {
        const int p = pp * 2 + ph;
        const int b = b0 + p;
        unsigned long long acc2a = 0ull, acc2b = 0ull;
        const ulonglong2* ap = (const ulonglong2*)arr[p];
#pragma unroll
        for (int q = 0; q < 16; ++q) {
            ulonglong2 v = ap[q];
            ffma2(acc2a, v.x, wp[2 * q]);
            ffma2(acc2b, v.y, wp[2 * q + 1]);
        }
        float2 sa = unpk(acc2a), sb = unpk(acc2b);
        float acc = bias + axs[p] * w0 + (sa.x + sa.y) + (sb.x + sb.y);
        float c = tanhf(acc);
        const int idx = n * NC + b * UNITS + u2;
        const float ug = g_UG[idx];
        g_S[idx] = ug * g_S[idx] + (1.f - ug) * c;
    }
}

// ---------------- output head: out[b,p,n] = state[b,n,:] @ Wo + bo ----------------
__global__ __launch_bounds__(128)
void final_kernel(const float* __restrict__ Wo, const float* __restrict__ bo,
                  float* __restrict__ out) {
    __shared__ float srow[NC];
    __shared__ float wo[UNITS * PRELEN];
    __shared__ float bos[PRELEN];
    const int n = blockIdx.x, j = threadIdx.x;
    for (int idx = j; idx < NC; idx += 128) srow[idx] = g_S[n * NC + idx];
    for (int idx = j; idx < UNITS * PRELEN; idx += 128) wo[idx] = Wo[idx];
    if (j < PRELEN) bos[j] = bo[j];
    __syncthreads();
    for (int o = j; o < BATCH * PRELEN; o += 128) {
        int b = o / PRELEN, p = o - b * PRELEN;
        float acc = bos[p];
#pragma unroll
        for (int u = 0; u < UNITS; ++u) acc += srow[b * UNITS + u] * wo[u * PRELEN + p];
        out[b * (PRELEN * N_NODES) + p * N_NODES + n] = acc;
    }
}

// ---------------- launch ----------------
extern "C" void kernel_launch(void* const* d_in, const int* in_sizes, int n_in,
                              void* d_out, int out_size) {
    const float* A  = (const float*)d_in[0];
    const float* X  = (const float*)d_in[1];
    const float* st = (const float*)d_in[2];
    const float* W1 = (const float*)d_in[3];
    const float* b1 = (const float*)d_in[4];
    const float* W2 = (const float*)d_in[5];
    const float* b2 = (const float*)d_in[6];
    const float* Wo = (const float*)d_in[7];
    const float* bo = (const float*)d_in[8];
    float* out = (float*)d_out;
    (void)in_sizes; (void)n_in; (void)out_size;

    float *pAS, *pAR, *pAX, *pAX2, *pS, *pRS;
    char *pAq, *pSq, *pRq, *pXq;
    cudaGetSymbolAddress((void**)&pAS,  g_AS);
    cudaGetSymbolAddress((void**)&pAR,  g_AR);
    cudaGetSymbolAddress((void**)&pAX,  g_AX);
    cudaGetSymbolAddress((void**)&pAX2, g_AX2);
    cudaGetSymbolAddress((void**)&pS,   g_S);
    cudaGetSymbolAddress((void**)&pRS,  g_RS);
    cudaGetSymbolAddress((void**)&pAq,  g_Aq);
    cudaGetSymbolAddress((void**)&pSq,  g_Sq);
    cudaGetSymbolAddress((void**)&pRq,  g_Rq);
    cudaGetSymbolAddress((void**)&pXq,  g_Xq);

    const int DSM = 3 * (int)STGB;   // 92160 B (x2 CTAs/SM = 184320 < 228KB)
    cudaFuncSetAttribute(imma_gemm, cudaFuncAttributeMaxDynamicSharedMemorySize, DSM);

    // one-time: quantize A and X; pack initial state
    quantA_kernel<<<(N_NODES * N_NODES + 255) / 256, 256>>>(A);
    quantX_kernel<<<(TB * N_NODES + 255) / 256, 256>>>(X);
    pack_s_kernel<<<(BATCH * N_NODES * UNITS + 255) / 256, 256>>>(st);

    // AX = A_hat @ X^T for all timesteps, K-split -> g_AX + g_AX2
    imma_gemm<<<dim3(TB / 64, N_NODES / 128, 2), 256, DSM>>>(pAX, pAX2, pAq, pXq, TB,
                                                             (size_t)TB * N_NODES);

    for (int t = 0; t < TSTEPS; ++t) {
        quantT_kernel<<<dim3(NC / 32, N_NODES / 32), dim3(32, 8)>>>(pS, pSq);
        // AS halves -> (g_AS, g_AR); gates1 sums them
        imma_gemm<<<dim3(NC / 64, N_NODES / 128, 2), 256, DSM>>>(pAS, pAR, pAq, pSq, NC,
                                                                 (size_t)NC * N_NODES);
        gates1_kernel<<<dim3(2, N_NODES), 128>>>(W1, b1, t);
        quantT_kernel<<<dim3(NC / 32, N_NODES / 32), dim3(32, 8)>>>(pRS, pRq);
        // AR halves -> (g_AS, g_AR); gates2 sums them
        imma_gemm<<<dim3(NC / 64, N_NODES / 128, 2), 256, DSM>>>(pAS, pAR, pAq, pRq, NC,
                                                                 (size_t)NC * N_NODES);
        gates2_kernel<<<dim3(2, N_NODES), 128>>>(W2, b2, t);
    }

    final_kernel<<<N_NODES, 128>>>(Wo, bo, out);
}

// round 14
// speedup vs baseline: 1.0370x; 1.0370x over previous
#include <cuda_runtime.h>
#include <cstdint>

// ---------------- problem constants ----------------
#define N_NODES 4096
#define UNITS   64
#define BATCH   32
#define TSTEPS  12
#define PRELEN  12
#define NC      2048                 // GEMM columns for state (b*64+u)
#define TB      384                  // t*32+b columns for X
#define A_PART  ((size_t)N_NODES * N_NODES)
#define ROWB    80u                  // smem row stride: 64B data + 16B pad
#define NKT     (N_NODES/64)         // 64 k-tiles of BK=64

// ---------------- scratch (device globals; no allocation allowed) ----------------
__device__ __align__(128) float g_S [N_NODES*NC];   // state fp32 [node][col]
__device__ __align__(128) float g_AS[N_NODES*NC];   // A @ S
__device__ __align__(128) float g_RS[N_NODES*NC];   // r * state
__device__ __align__(128) float g_AR[N_NODES*NC];   // A @ RS
__device__ __align__(128) float g_UG[N_NODES*NC];   // u gate
__device__ __align__(128) float g_AX[N_NODES*TB];   // A @ X (all steps)
__device__ __align__(128) char g_Aq[2*A_PART];                // A planes: a1 | a0, [m][k]
__device__ __align__(128) char g_Sq[2*(size_t)NC*N_NODES];    // S planes: b1 | b0, [n][k]
__device__ __align__(128) char g_Rq[2*(size_t)NC*N_NODES];    // RS planes
__device__ __align__(128) char g_Xq[2*(size_t)TB*N_NODES];    // X planes

// ---------------- PTX helpers (baseline PTX, sm_80+) ----------------
__device__ __forceinline__ uint32_t s2u(const void* p) {
    uint32_t a;
    asm("{ .reg .u64 t; cvta.to.shared.u64 t, %1; cvt.u32.u64 %0, t; }" : "=r"(a) : "l"(p));
    return a;
}
__device__ __forceinline__ void cp16(uint32_t dst, const void* src) {
    asm volatile("cp.async.cg.shared.global [%0], [%1], 16;" :: "r"(dst), "l"(src) : "memory");
}
__device__ __forceinline__ void cp_commit() {
    asm volatile("cp.async.commit_group;" ::: "memory");
}
template<int N>
__device__ __forceinline__ void cp_wait() {
    asm volatile("cp.async.wait_group %0;" :: "n"(N) : "memory");
}
__device__ __forceinline__ void ldm_x4(uint32_t* r, uint32_t a) {
    asm volatile("ldmatrix.sync.aligned.m8n8.x4.shared.b16 {%0,%1,%2,%3}, [%4];"
                 : "=r"(r[0]), "=r"(r[1]), "=r"(r[2]), "=r"(r[3]) : "r"(a));
}
// int8 IMMA m16n8k32, s32 accum
__device__ __forceinline__ void imma_u8s8(int* d, const uint32_t* a, const uint32_t* b) {
    asm volatile(
        "mma.sync.aligned.m16n8k32.row.col.s32.u8.s8.s32 "
        "{%0,%1,%2,%3}, {%4,%5,%6,%7}, {%8,%9}, {%0,%1,%2,%3};"
        : "+r"(d[0]), "+r"(d[1]), "+r"(d[2]), "+r"(d[3])
        : "r"(a[0]), "r"(a[1]), "r"(a[2]), "r"(a[3]), "r"(b[0]), "r"(b[1]));
}
__device__ __forceinline__ void imma_s8s8(int* d, const uint32_t* a, const uint32_t* b) {
    asm volatile(
        "mma.sync.aligned.m16n8k32.row.col.s32.s8.s8.s32 "
        "{%0,%1,%2,%3}, {%4,%5,%6,%7}, {%8,%9}, {%0,%1,%2,%3};"
        : "+r"(d[0]), "+r"(d[1]), "+r"(d[2]), "+r"(d[3])
        : "r"(a[0]), "r"(a[1]), "r"(a[2]), "r"(a[3]), "r"(b[0]), "r"(b[1]));
}
// packed fp32x2 FMA (Blackwell FFMA2)
__device__ __forceinline__ void ffma2(unsigned long long &d,
                                      unsigned long long a,
                                      unsigned long long b) {
    asm("fma.rn.f32x2 %0, %1, %2, %0;" : "+l"(d) : "l"(a), "l"(b));
}
__device__ __forceinline__ unsigned long long pk2(float x, float y) {
    unsigned long long r;
    asm("mov.b64 %0, {%1, %2};" : "=l"(r)
        : "r"(__float_as_uint(x)), "r"(__float_as_uint(y)));
    return r;
}
__device__ __forceinline__ float2 unpk(unsigned long long v) {
    unsigned int lo, hi;
    asm("mov.b64 {%0, %1}, %2;" : "=r"(lo), "=r"(hi) : "l"(v));
    return make_float2(__uint_as_float(lo), __uint_as_float(hi));
}

// ---------------- IMMA fixed-point split-GEMM (R12 config — no K-split) ----------------
// C[m,n] = sum_k A[m,k]*B[n,k]; A = (a1*256 + a0)*2^-26, B = (b1*256 + b0)*2^-12.
// C = (acc_hh*65536 + acc_x*256)*2^-38 (dropped a0*b0: centered, zero-mean).
// CTA tile 128x64, 256 threads (2 CTAs/SM), warp grid 4m x 2n, warp tile 32x32.
// BK=64, 3-stage cp.async pipeline.
#define A0_OFF 10240u
#define B1_OFF 20480u
#define B0_OFF 25600u
#define STGB   30720u

__global__ __launch_bounds__(256, 2)
void imma_gemm(float* __restrict__ C, const char* __restrict__ Aq,
               const char* __restrict__ Bq, int ncols, size_t bPart) {
    extern __shared__ __align__(128) char smem[];
    const uint32_t sm0 = s2u(smem);

    const int tid = threadIdx.x;
    const int lane = tid & 31, wid = tid >> 5;
    const int wm = wid & 3, wn = wid >> 2;          // 4m x 2n warps, 32x32 tiles
    const int m0 = blockIdx.y * 128;
    const int n0 = blockIdx.x * 64;

    int acc_hh[2][4][4], acc_x[2][4][4];
#pragma unroll
    for (int i = 0; i < 2; ++i)
#pragma unroll
        for (int j = 0; j < 4; ++j)
#pragma unroll
            for (int q = 0; q < 4; ++q) { acc_hh[i][j][q] = 0; acc_x[i][j][q] = 0; }

    auto load_stage = [&](int kt) {
        const uint32_t sb = sm0 + (uint32_t)(kt % 3) * STGB;
        const size_t k0 = (size_t)kt * 64;
#pragma unroll
        for (int it = 0; it < 6; ++it) {
            const int i = tid + it * 256;           // 0..1535 16B chunks
            const int chunk = i & 3;                // 4 chunks = 64B row
            const int row = i >> 2;                 // 0..383
            const char* src;
            uint32_t rel;
            if (row < 256) {                        // A planes: a1 rows 0-127, a0 128-255
                const int plane = row >> 7, m = row & 127;
                src = Aq + (size_t)plane * A_PART + (size_t)(m0 + m) * N_NODES + k0;
                rel = (uint32_t)plane * A0_OFF + (uint32_t)m * ROWB;
            } else {                                // B planes: b1 rows 256-319, b0 320-383
                const int r = row - 256;
                const int plane = r >> 6, n = r & 63;
                src = Bq + (size_t)plane * bPart + (size_t)(n0 + n) * N_NODES + k0;
                rel = B1_OFF + (uint32_t)plane * (B0_OFF - B1_OFF) + (uint32_t)n * ROWB;
            }
            cp16(sb + rel + (uint32_t)chunk * 16u, src + chunk * 16);
        }
        cp_commit();
    };

    load_stage(0);
    load_stage(1);

    const uint32_t aLane = (uint32_t)(lane & 15) * ROWB + (uint32_t)((lane >> 4) << 4);
    const uint32_t bLane = (uint32_t)(((lane >> 4) << 3) + (lane & 7)) * ROWB
                         + (uint32_t)(((lane >> 3) & 1) << 4);

#pragma unroll 1
    for (int kt = 0; kt < NKT; ++kt) {
        if (kt < NKT - 1) cp_wait<1>();
        else              cp_wait<0>();
        __syncthreads();
        if (kt + 2 < NKT) load_stage(kt + 2);

        const uint32_t sb = sm0 + (uint32_t)(kt % 3) * STGB;
        const uint32_t aBase1 = sb + (uint32_t)(wm * 32) * ROWB + aLane;
        const uint32_t bBase1 = sb + B1_OFF + (uint32_t)(wn * 32) * ROWB + bLane;

#pragma unroll
        for (int ks = 0; ks < 2; ++ks) {
            const uint32_t kb = (uint32_t)(ks * 32);        // 32 int8 = 32B
            uint32_t fb1[4][2], fb0[4][2];
#pragma unroll
            for (int nf2 = 0; nf2 < 2; ++nf2) {
                const uint32_t off = (uint32_t)(nf2 * 16) * ROWB + kb;
                uint32_t t1[4], t0[4];
                ldm_x4(t1, bBase1 + off);
                ldm_x4(t0, bBase1 + off + (B0_OFF - B1_OFF));
                fb1[2 * nf2][0] = t1[0]; fb1[2 * nf2][1] = t1[1];
                fb1[2 * nf2 + 1][0] = t1[2]; fb1[2 * nf2 + 1][1] = t1[3];
                fb0[2 * nf2][0] = t0[0]; fb0[2 * nf2][1] = t0[1];
                fb0[2 * nf2 + 1][0] = t0[2]; fb0[2 * nf2 + 1][1] = t0[3];
            }
#pragma unroll
            for (int mf = 0; mf < 2; ++mf) {
                const uint32_t aa = aBase1 + (uint32_t)(mf * 16) * ROWB + kb;
                uint32_t fa1[4], fa0[4];
                ldm_x4(fa1, aa);
                ldm_x4(fa0, aa + A0_OFF);
#pragma unroll
                for (int nf = 0; nf < 4; ++nf) imma_u8s8(acc_hh[mf][nf], fa1, fb1[nf]);
#pragma unroll
                for (int nf = 0; nf < 4; ++nf) imma_u8s8(acc_x[mf][nf], fa1, fb0[nf]);
#pragma unroll
                for (int nf = 0; nf < 4; ++nf) imma_s8s8(acc_x[mf][nf], fa0, fb1[nf]);
            }
        }
    }

    // epilogue: C = (hh*2^16 + cross*2^8) * 2^-38
    const float SC = 3.637978807091713e-12f;   // 2^-38
    const int grp = lane >> 2, tl = lane & 3;
#pragma unroll
    for (int mf = 0; mf < 2; ++mf) {
#pragma unroll
        for (int nf = 0; nf < 4; ++nf) {
            const int row = m0 + wm * 32 + mf * 16 + grp;
            const int col = n0 + wn * 32 + nf * 8 + tl * 2;
            float* p0 = C + (size_t)row * ncols + col;
            float* p1 = C + (size_t)(row + 8) * ncols + col;
            p0[0] = ((float)acc_hh[mf][nf][0] * 65536.f + (float)acc_x[mf][nf][0] * 256.f) * SC;
            p0[1] = ((float)acc_hh[mf][nf][1] * 65536.f + (float)acc_x[mf][nf][1] * 256.f) * SC;
            p1[0] = ((float)acc_hh[mf][nf][2] * 65536.f + (float)acc_x[mf][nf][2] * 256.f) * SC;
            p1[1] = ((float)acc_hh[mf][nf][3] * 65536.f + (float)acc_x[mf][nf][3] * 256.f) * SC;
        }
    }
}

// ---------------- quantize A (once): A in [0, 2^-12) -> 16-bit fixed, planes a1|a0 ----------------
__global__ void quantA_kernel(const float* __restrict__ in) {
    int i = blockIdx.x * blockDim.x + threadIdx.x;
    if (i < N_NODES * N_NODES) {
        int q = (int)rintf(in[i] * 67108864.f);    // 2^26, <= 16384
        int h = (q + 128) >> 8;                     // [0,64]
        g_Aq[i] = (char)h;
        g_Aq[A_PART + i] = (char)(q - (h << 8));    // [-128,127]
    }
}

// ---------------- quantize B helper ----------------
__device__ __forceinline__ void quantB(float v, char& b1, char& b0) {
    v = fminf(fmaxf(v, -7.93f), 7.93f);
    int q = (int)rintf(v * 4096.f);                 // 2^12, |q| <= 32481
    int h = (q + 128) >> 8;                          // [-126,127]
    b1 = (char)h;
    b0 = (char)(q - (h << 8));                       // [-128,127]
}

// ---------------- quantize X (already [tb][node] k-contiguous) ----------------
__global__ void quantX_kernel(const float* __restrict__ X) {
    int i = blockIdx.x * blockDim.x + threadIdx.x;
    if (i < TB * N_NODES) {
        char b1, b0;
        quantB(X[i], b1, b0);
        g_Xq[i] = b1;
        g_Xq[(size_t)TB * N_NODES + i] = b0;
    }
}

// ---------------- transpose + quantize: fp32 [node][col] -> int8 planes [col][node] ----------------
__global__ __launch_bounds__(256)
void quantT_kernel(const float* __restrict__ in, char* __restrict__ out) {
    __shared__ float tile[32][33];
    const int col0 = blockIdx.x * 32, node0 = blockIdx.y * 32;
    const int tx = threadIdx.x, ty = threadIdx.y;
#pragma unroll
    for (int j = 0; j < 32; j += 8)
        tile[ty + j][tx] = in[(size_t)(node0 + ty + j) * NC + col0 + tx];
    __syncthreads();
#pragma unroll
    for (int j = 0; j < 32; j += 8) {
        char b1, b0;
        quantB(tile[tx][ty + j], b1, b0);
        size_t o = (size_t)(col0 + ty + j) * N_NODES + node0 + tx;
        out[o] = b1;
        out[(size_t)NC * N_NODES + o] = b0;
    }
}

// ---------------- input packing: state -> [node][col] fp32 ----------------
__global__ void pack_s_kernel(const float* __restrict__ st) {
    int i = blockIdx.x * blockDim.x + threadIdx.x;  // over B*N*U
    if (i < BATCH * N_NODES * UNITS) {
        int u = i & 63;
        int n = (i >> 6) & (N_NODES - 1);
        int b = i >> 18;
        g_S[n * NC + b * UNITS + u] = st[i];
    }
}

// ---------------- gate 1: v1 = sigmoid(gc1); scatter r*state -> RS, u -> UG ----------------
// One block per v1-node, ALL 32 batches (weights loaded once per node).
// TGCN chunk(2,dim=1) quirk on flattened (N,2U):
//   v1[b,n,j] is r for node 2n+(j>>6), unit j&63   when n < 2048
//   v1[b,n,j] is u for node 2(n-2048)+(j>>6)       when n >= 2048
__global__ __launch_bounds__(128)
void gates1_kernel(const float* __restrict__ W1, const float* __restrict__ b1, int t) {
    __shared__ __align__(16) float asr[32][64];
    __shared__ float axs[32];
    const int j  = threadIdx.x;          // 0..127 output feature
    const int n  = blockIdx.x;           // v1 node
    const float w0 = W1[j];
    unsigned long long wp[32];           // pairs (w[2q+1], w[2q+2])
#pragma unroll
    for (int q = 0; q < 32; ++q)
        wp[q] = pk2(W1[(2 * q + 1) * 128 + j], W1[(2 * q + 2) * 128 + j]);
    const float bias = b1[j];

    const float* src = g_AS + n * NC;
    for (int idx = j; idx < 2048; idx += 128) ((float*)asr)[idx] = src[idx];
    if (j < 32) axs[j] = g_AX[n * TB + t * BATCH + j];
    __syncthreads();

    const int jh = j >> 6, u2 = j & 63;
    for (int p = 0; p < 32; ++p) {
        unsigned long long acc2a = 0ull, acc2b = 0ull;
        const ulonglong2* ap = (const ulonglong2*)asr[p];
#pragma unroll
        for (int q = 0; q < 16; ++q) {
            ulonglong2 v = ap[q];
            ffma2(acc2a, v.x, wp[2 * q]);
            ffma2(acc2b, v.y, wp[2 * q + 1]);
        }
        float2 sa = unpk(acc2a), sb = unpk(acc2b);
        float acc = bias + axs[p] * w0 + (sa.x + sa.y) + (sb.x + sb.y);
        float sg = 1.f / (1.f + __expf(-acc));
        if (n < 2048) {
            const int idx = (2 * n + jh) * NC + p * UNITS + u2;
            g_RS[idx] = sg * g_S[idx];
        } else {
            g_UG[(2 * (n - 2048) + jh) * NC + p * UNITS + u2] = sg;
        }
    }
}

// ---------------- gate 2: c = tanh(gc2); state = u*state + (1-u)*c ----------------
// One block per node, ALL 32 batches.
__global__ __launch_bounds__(128)
void gates2_kernel(const float* __restrict__ W2, const float* __restrict__ b2, int t) {
    __shared__ __align__(16) float arr[32][64];
    __shared__ float axs[32];
    const int j  = threadIdx.x;
    const int n  = blockIdx.x;           // real node
    const int u2 = j & 63, ph = j >> 6;
    const float w0 = W2[u2];
    unsigned long long wp[32];           // pairs (w[2q+1], w[2q+2])
#pragma unroll
    for (int q = 0; q < 32; ++q)
        wp[q] = pk2(W2[(2 * q + 1) * 64 + u2], W2[(2 * q + 2) * 64 + u2]);
    const float bias = b2[u2];

    const float* src = g_AR + n * NC;
    for (int idx = j; idx < 2048; idx += 128) ((float*)arr)[idx] = src[idx];
    if (j < 32) axs[j] = g_AX[n * TB + t * BATCH + j];
    __syncthreads();

    for (int pp = 0; pp < 16; ++pp) {
        const int p = pp * 2 + ph;
        unsigned long long acc2a = 0ull, acc2b = 0ull;
        const ulonglong2* ap = (const ulonglong2*)arr[p];
#pragma unroll
        for (int q = 0; q < 16; ++q) {
            ulonglong2 v = ap[q];
            ffma2(acc2a, v.x, wp[2 * q]);
            ffma2(acc2b, v.y, wp[2 * q + 1]);
        }
        float2 sa = unpk(acc2a), sb = unpk(acc2b);
        float acc = bias + axs[p] * w0 + (sa.x + sa.y) + (sb.x + sb.y);
        float c = tanhf(acc);
        const int idx = n * NC + p * UNITS + u2;
        const float ug = g_UG[idx];
        g_S[idx] = ug * g_S[idx] + (1.f - ug) * c;
    }
}

// ---------------- output head: out[b,p,n] = state[b,n,:] @ Wo + bo ----------------
__global__ __launch_bounds__(128)
void final_kernel(const float* __restrict__ Wo, const float* __restrict__ bo,
                  float* __restrict__ out) {
    __shared__ float srow[NC];
    __shared__ float wo[UNITS * PRELEN];
    __shared__ float bos[PRELEN];
    const int n = blockIdx.x, j = threadIdx.x;
    for (int idx = j; idx < NC; idx += 128) srow[idx] = g_S[n * NC + idx];
    for (int idx = j; idx < UNITS * PRELEN; idx += 128) wo[idx] = Wo[idx];
    if (j < PRELEN) bos[j] = bo[j];
    __syncthreads();
    for (int o = j; o < BATCH * PRELEN; o += 128) {
        int b = o / PRELEN, p = o - b * PRELEN;
        float acc = bos[p];
#pragma unroll
        for (int u = 0; u < UNITS; ++u) acc += srow[b * UNITS + u] * wo[u * PRELEN + p];
        out[b * (PRELEN * N_NODES) + p * N_NODES + n] = acc;
    }
}

// ---------------- launch ----------------
extern "C" void kernel_launch(void* const* d_in, const int* in_sizes, int n_in,
                              void* d_out, int out_size) {
    const float* A  = (const float*)d_in[0];
    const float* X  = (const float*)d_in[1];
    const float* st = (const float*)d_in[2];
    const float* W1 = (const float*)d_in[3];
    const float* b1 = (const float*)d_in[4];
    const float* W2 = (const float*)d_in[5];
    const float* b2 = (const float*)d_in[6];
    const float* Wo = (const float*)d_in[7];
    const float* bo = (const float*)d_in[8];
    float* out = (float*)d_out;
    (void)in_sizes; (void)n_in; (void)out_size;

    float *pAS, *pAR, *pAX, *pS, *pRS;
    char *pAq, *pSq, *pRq, *pXq;
    cudaGetSymbolAddress((void**)&pAS, g_AS);
    cudaGetSymbolAddress((void**)&pAR, g_AR);
    cudaGetSymbolAddress((void**)&pAX, g_AX);
    cudaGetSymbolAddress((void**)&pS,  g_S);
    cudaGetSymbolAddress((void**)&pRS, g_RS);
    cudaGetSymbolAddress((void**)&pAq, g_Aq);
    cudaGetSymbolAddress((void**)&pSq, g_Sq);
    cudaGetSymbolAddress((void**)&pRq, g_Rq);
    cudaGetSymbolAddress((void**)&pXq, g_Xq);

    const int DSM = 3 * (int)STGB;   // 92160 B (x2 CTAs/SM = 184320 < 228KB)
    cudaFuncSetAttribute(imma_gemm, cudaFuncAttributeMaxDynamicSharedMemorySize, DSM);

    // one-time: quantize A and X; pack initial state
    quantA_kernel<<<(N_NODES * N_NODES + 255) / 256, 256>>>(A);
    quantX_kernel<<<(TB * N_NODES + 255) / 256, 256>>>(X);
    pack_s_kernel<<<(BATCH * N_NODES * UNITS + 255) / 256, 256>>>(st);

    // AX = A_hat @ X^T for all timesteps (6x32 = 192 CTAs -> single wave)
    imma_gemm<<<dim3(TB / 64, N_NODES / 128), 256, DSM>>>(pAX, pAq, pXq, TB,
                                                          (size_t)TB * N_NODES);

    for (int t = 0; t < TSTEPS; ++t) {
        quantT_kernel<<<dim3(NC / 32, N_NODES / 32), dim3(32, 8)>>>(pS, pSq);
        imma_gemm<<<dim3(NC / 64, N_NODES / 128), 256, DSM>>>(pAS, pAq, pSq, NC,
                                                              (size_t)NC * N_NODES);
        gates1_kernel<<<N_NODES, 128>>>(W1, b1, t);
        quantT_kernel<<<dim3(NC / 32, N_NODES / 32), dim3(32, 8)>>>(pRS, pRq);
        imma_gemm<<<dim3(NC / 64, N_NODES / 128), 256, DSM>>>(pAR, pAq, pRq, NC,
                                                              (size_t)NC * N_NODES);
        gates2_kernel<<<N_NODES, 128>>>(W2, b2, t);
    }

    final_kernel<<<N_NODES, 128>>>(Wo, bo, out);
}

// round 16
// speedup vs baseline: 1.0381x; 1.0011x over previous
#include <cuda_runtime.h>
#include <cstdint>

// ---------------- problem constants ----------------
#define N_NODES 4096
#define UNITS   64
#define BATCH   32
#define TSTEPS  12
#define PRELEN  12
#define NC      2048                 // GEMM columns for state (b*64+u)
#define TB      384                  // t*32+b columns for X
#define A_PART  ((size_t)N_NODES * N_NODES)
#define ROWB    80u                  // smem row stride: 64B data + 16B pad
#define NKT     (N_NODES/64)         // 64 k-tiles of BK=64

// ---------------- scratch (device globals; no allocation allowed) ----------------
__device__ __align__(128) float g_S [N_NODES*NC];   // state fp32 [node][col]
__device__ __align__(128) float g_AS[N_NODES*NC];   // A @ S
__device__ __align__(128) float g_RS[N_NODES*NC];   // r * state
__device__ __align__(128) float g_AR[N_NODES*NC];   // A @ RS
__device__ __align__(128) float g_UG[N_NODES*NC];   // u gate
__device__ __align__(128) float g_AX[N_NODES*TB];   // A @ X (all steps)
__device__ __align__(128) char g_Aq[2*A_PART];                // A planes: a1 | a0, [m][k]
__device__ __align__(128) char g_Sq[2*(size_t)NC*N_NODES];    // S planes: b1 | b0, [n][k]
__device__ __align__(128) char g_Rq[2*(size_t)NC*N_NODES];    // RS planes
__device__ __align__(128) char g_Xq[2*(size_t)TB*N_NODES];    // X planes

// ---------------- PTX helpers (baseline PTX, sm_80+) ----------------
__device__ __forceinline__ uint32_t s2u(const void* p) {
    uint32_t a;
    asm("{ .reg .u64 t; cvta.to.shared.u64 t, %1; cvt.u32.u64 %0, t; }" : "=r"(a) : "l"(p));
    return a;
}
__device__ __forceinline__ void cp16(uint32_t dst, const void* src) {
    asm volatile("cp.async.cg.shared.global [%0], [%1], 16;" :: "r"(dst), "l"(src) : "memory");
}
__device__ __forceinline__ void cp_commit() {
    asm volatile("cp.async.commit_group;" ::: "memory");
}
template<int N>
__device__ __forceinline__ void cp_wait() {
    asm volatile("cp.async.wait_group %0;" :: "n"(N) : "memory");
}
__device__ __forceinline__ void ldm_x4(uint32_t* r, uint32_t a) {
    asm volatile("ldmatrix.sync.aligned.m8n8.x4.shared.b16 {%0,%1,%2,%3}, [%4];"
                 : "=r"(r[0]), "=r"(r[1]), "=r"(r[2]), "=r"(r[3]) : "r"(a));
}
// int8 IMMA m16n8k32, s32 accum — uniform s8.s8 (a1 in [0,64] is s8-safe)
__device__ __forceinline__ void imma_s8s8(int* d, const uint32_t* a, const uint32_t* b) {
    asm volatile(
        "mma.sync.aligned.m16n8k32.row.col.s32.s8.s8.s32 "
        "{%0,%1,%2,%3}, {%4,%5,%6,%7}, {%8,%9}, {%0,%1,%2,%3};"
        : "+r"(d[0]), "+r"(d[1]), "+r"(d[2]), "+r"(d[3])
        : "r"(a[0]), "r"(a[1]), "r"(a[2]), "r"(a[3]), "r"(b[0]), "r"(b[1]));
}
// packed fp32x2 FMA (Blackwell FFMA2)
__device__ __forceinline__ void ffma2(unsigned long long &d,
                                      unsigned long long a,
                                      unsigned long long b) {
    asm("fma.rn.f32x2 %0, %1, %2, %0;" : "+l"(d) : "l"(a), "l"(b));
}
__device__ __forceinline__ unsigned long long pk2(float x, float y) {
    unsigned long long r;
    asm("mov.b64 %0, {%1, %2};" : "=l"(r)
        : "r"(__float_as_uint(x)), "r"(__float_as_uint(y)));
    return r;
}
__device__ __forceinline__ float2 unpk(unsigned long long v) {
    unsigned int lo, hi;
    asm("mov.b64 {%0, %1}, %2;" : "=r"(lo), "=r"(hi) : "l"(v));
    return make_float2(__uint_as_float(lo), __uint_as_float(hi));
}

// ---------------- IMMA fixed-point split-GEMM ----------------
// C[m,n] = sum_k A[m,k]*B[n,k]; A = (a1*256 + a0)*2^-26, B = (b1*256 + b0)*2^-12.
// C = (acc_hh*65536 + acc_x*256)*2^-38 (dropped a0*b0: centered, zero-mean).
// CTA tile 128x64, 256 threads (2 CTAs/SM), warp grid 4m x 2n, warp tile 32x32.
// BK=64, 3-stage cp.async pipeline.
#define A0_OFF 10240u
#define B1_OFF 20480u
#define B0_OFF 25600u
#define STGB   30720u

__global__ __launch_bounds__(256, 2)
void imma_gemm(float* __restrict__ C, const char* __restrict__ Aq,
               const char* __restrict__ Bq, int ncols, size_t bPart) {
    extern __shared__ __align__(128) char smem[];
    const uint32_t sm0 = s2u(smem);

    const int tid = threadIdx.x;
    const int lane = tid & 31, wid = tid >> 5;
    const int wm = wid & 3, wn = wid >> 2;          // 4m x 2n warps, 32x32 tiles
    const int m0 = blockIdx.y * 128;
    const int n0 = blockIdx.x * 64;

    int acc_hh[2][4][4], acc_x[2][4][4];
#pragma unroll
    for (int i = 0; i < 2; ++i)
#pragma unroll
        for (int j = 0; j < 4; ++j)
#pragma unroll
            for (int q = 0; q < 4; ++q) { acc_hh[i][j][q] = 0; acc_x[i][j][q] = 0; }

    auto load_stage = [&](int kt) {
        const uint32_t sb = sm0 + (uint32_t)(kt % 3) * STGB;
        const size_t k0 = (size_t)kt * 64;
#pragma unroll
        for (int it = 0; it < 6; ++it) {
            const int i = tid + it * 256;           // 0..1535 16B chunks
            const int chunk = i & 3;                // 4 chunks = 64B row
            const int row = i >> 2;                 // 0..383
            const char* src;
            uint32_t rel;
            if (row < 256) {                        // A planes: a1 rows 0-127, a0 128-255
                const int plane = row >> 7, m = row & 127;
                src = Aq + (size_t)plane * A_PART + (size_t)(m0 + m) * N_NODES + k0;
                rel = (uint32_t)plane * A0_OFF + (uint32_t)m * ROWB;
            } else {                                // B planes: b1 rows 256-319, b0 320-383
                const int r = row - 256;
                const int plane = r >> 6, n = r & 63;
                src = Bq + (size_t)plane * bPart + (size_t)(n0 + n) * N_NODES + k0;
                rel = B1_OFF + (uint32_t)plane * (B0_OFF - B1_OFF) + (uint32_t)n * ROWB;
            }
            cp16(sb + rel + (uint32_t)chunk * 16u, src + chunk * 16);
        }
        cp_commit();
    };

    load_stage(0);
    load_stage(1);

    const uint32_t aLane = (uint32_t)(lane & 15) * ROWB + (uint32_t)((lane >> 4) << 4);
    const uint32_t bLane = (uint32_t)(((lane >> 4) << 3) + (lane & 7)) * ROWB
                         + (uint32_t)(((lane >> 3) & 1) << 4);

#pragma unroll 1
    for (int kt = 0; kt < NKT; ++kt) {
        if (kt < NKT - 1) cp_wait<1>();
        else              cp_wait<0>();
        __syncthreads();
        if (kt + 2 < NKT) load_stage(kt + 2);

        const uint32_t sb = sm0 + (uint32_t)(kt % 3) * STGB;
        const uint32_t aBase1 = sb + (uint32_t)(wm * 32) * ROWB + aLane;
        const uint32_t bBase1 = sb + B1_OFF + (uint32_t)(wn * 32) * ROWB + bLane;

#pragma unroll
        for (int ks = 0; ks < 2; ++ks) {
            const uint32_t kb = (uint32_t)(ks * 32);        // 32 int8 = 32B
            uint32_t fb1[4][2], fb0[4][2];
#pragma unroll
            for (int nf2 = 0; nf2 < 2; ++nf2) {
                const uint32_t off = (uint32_t)(nf2 * 16) * ROWB + kb;
                uint32_t t1[4], t0[4];
                ldm_x4(t1, bBase1 + off);
                ldm_x4(t0, bBase1 + off + (B0_OFF - B1_OFF));
                fb1[2 * nf2][0] = t1[0]; fb1[2 * nf2][1] = t1[1];
                fb1[2 * nf2 + 1][0] = t1[2]; fb1[2 * nf2 + 1][1] = t1[3];
                fb0[2 * nf2][0] = t0[0]; fb0[2 * nf2][1] = t0[1];
                fb0[2 * nf2 + 1][0] = t0[2]; fb0[2 * nf2 + 1][1] = t0[3];
            }
#pragma unroll
            for (int mf = 0; mf < 2; ++mf) {
                const uint32_t aa = aBase1 + (uint32_t)(mf * 16) * ROWB + kb;
                uint32_t fa1[4], fa0[4];
                ldm_x4(fa1, aa);
                ldm_x4(fa0, aa + A0_OFF);
#pragma unroll
                for (int nf = 0; nf < 4; ++nf) imma_s8s8(acc_hh[mf][nf], fa1, fb1[nf]);
#pragma unroll
                for (int nf = 0; nf < 4; ++nf) imma_s8s8(acc_x[mf][nf], fa1, fb0[nf]);
#pragma unroll
                for (int nf = 0; nf < 4; ++nf) imma_s8s8(acc_x[mf][nf], fa0, fb1[nf]);
            }
        }
    }

    // epilogue: C = (hh*2^16 + cross*2^8) * 2^-38
    const float SC = 3.637978807091713e-12f;   // 2^-38
    const int grp = lane >> 2, tl = lane & 3;
#pragma unroll
    for (int mf = 0; mf < 2; ++mf) {
#pragma unroll
        for (int nf = 0; nf < 4; ++nf) {
            const int row = m0 + wm * 32 + mf * 16 + grp;
            const int col = n0 + wn * 32 + nf * 8 + tl * 2;
            float* p0 = C + (size_t)row * ncols + col;
            float* p1 = C + (size_t)(row + 8) * ncols + col;
            p0[0] = ((float)acc_hh[mf][nf][0] * 65536.f + (float)acc_x[mf][nf][0] * 256.f) * SC;
            p0[1] = ((float)acc_hh[mf][nf][1] * 65536.f + (float)acc_x[mf][nf][1] * 256.f) * SC;
            p1[0] = ((float)acc_hh[mf][nf][2] * 65536.f + (float)acc_x[mf][nf][2] * 256.f) * SC;
            p1[1] = ((float)acc_hh[mf][nf][3] * 65536.f + (float)acc_x[mf][nf][3] * 256.f) * SC;
        }
    }
}

// ---------------- quantize A (once): A in [0, 2^-12) -> 16-bit fixed, planes a1|a0 ----------------
__global__ void quantA_kernel(const float* __restrict__ in) {
    int i = blockIdx.x * blockDim.x + threadIdx.x;
    if (i < N_NODES * N_NODES) {
        int q = (int)rintf(in[i] * 67108864.f);    // 2^26, <= 16384
        int h = (q + 128) >> 8;                     // [0,64]
        g_Aq[i] = (char)h;
        g_Aq[A_PART + i] = (char)(q - (h << 8));    // [-128,127]
    }
}

// ---------------- quantize B helper ----------------
__device__ __forceinline__ void quantB(float v, char& b1, char& b0) {
    v = fminf(fmaxf(v, -7.93f), 7.93f);
    int q = (int)rintf(v * 4096.f);                 // 2^12, |q| <= 32481
    int h = (q + 128) >> 8;                          // [-126,127]
    b1 = (char)h;
    b0 = (char)(q - (h << 8));                       // [-128,127]
}

// ---------------- quantize X (already [tb][node] k-contiguous) ----------------
__global__ void quantX_kernel(const float* __restrict__ X) {
    int i = blockIdx.x * blockDim.x + threadIdx.x;
    if (i < TB * N_NODES) {
        char b1, b0;
        quantB(X[i], b1, b0);
        g_Xq[i] = b1;
        g_Xq[(size_t)TB * N_NODES + i] = b0;
    }
}

// ---------------- transpose + quantize: fp32 [node][col] -> int8 planes [col][node] ----------------
// Writes vectorized as char4 (4 nodes per store).
__global__ __launch_bounds__(256)
void quantT_kernel(const float* __restrict__ in, char* __restrict__ out) {
    __shared__ float tile[32][33];
    const int col0 = blockIdx.x * 32, node0 = blockIdx.y * 32;
    const int tx = threadIdx.x & 31, ty = threadIdx.x >> 5;   // 32 x 8
#pragma unroll
    for (int j = 0; j < 32; j += 8)
        tile[ty + j][tx] = in[(size_t)(node0 + ty + j) * NC + col0 + tx];
    __syncthreads();
    // 256 threads: col = tid>>3 (0..31), grp = tid&7 -> nodes 4grp..4grp+3
    const int col = threadIdx.x >> 3, grp = threadIdx.x & 7;
    char4 v1, v0;
    char b1, b0;
    quantB(tile[4 * grp + 0][col], b1, b0); v1.x = b1; v0.x = b0;
    quantB(tile[4 * grp + 1][col], b1, b0); v1.y = b1; v0.y = b0;
    quantB(tile[4 * grp + 2][col], b1, b0); v1.z = b1; v0.z = b0;
    quantB(tile[4 * grp + 3][col], b1, b0); v1.w = b1; v0.w = b0;
    const size_t o = (size_t)(col0 + col) * N_NODES + node0 + 4 * grp;
    *(char4*)(out + o) = v1;
    *(char4*)(out + (size_t)NC * N_NODES + o) = v0;
}

// ---------------- input packing: state -> [node][col] fp32 ----------------
__global__ void pack_s_kernel(const float* __restrict__ st) {
    int i = blockIdx.x * blockDim.x + threadIdx.x;  // over B*N*U
    if (i < BATCH * N_NODES * UNITS) {
        int u = i & 63;
        int n = (i >> 6) & (N_NODES - 1);
        int b = i >> 18;
        g_S[n * NC + b * UNITS + u] = st[i];
    }
}

// ---------------- gate 1: v1 = sigmoid(gc1); scatter r*state -> RS, u -> UG ----------------
// One block per v1-node, ALL 32 batches (weights loaded once per node).
// TGCN chunk(2,dim=1) quirk on flattened (N,2U):
//   v1[b,n,j] is r for node 2n+(j>>6), unit j&63   when n < 2048
//   v1[b,n,j] is u for node 2(n-2048)+(j>>6)       when n >= 2048
__global__ __launch_bounds__(128)
void gates1_kernel(const float* __restrict__ W1, const float* __restrict__ b1, int t) {
    __shared__ __align__(16) float asr[32][64];
    __shared__ float axs[32];
    const int j  = threadIdx.x;          // 0..127 output feature
    const int n  = blockIdx.x;           // v1 node
    const float w0 = W1[j];
    unsigned long long wp[32];           // pairs (w[2q+1], w[2q+2])
#pragma unroll
    for (int q = 0; q < 32; ++q)
        wp[q] = pk2(W1[(2 * q + 1) * 128 + j], W1[(2 * q + 2) * 128 + j]);
    const float bias = b1[j];

    const float* src = g_AS + n * NC;
    for (int idx = j; idx < 2048; idx += 128) ((float*)asr)[idx] = src[idx];
    if (j < 32) axs[j] = g_AX[n * TB + t * BATCH + j];
    __syncthreads();

    const int jh = j >> 6, u2 = j & 63;
    for (int p = 0; p < 32; ++p) {
        unsigned long long acc2a = 0ull, acc2b = 0ull;
        const ulonglong2* ap = (const ulonglong2*)asr[p];
#pragma unroll
        for (int q = 0; q < 16; ++q) {
            ulonglong2 v = ap[q];
            ffma2(acc2a, v.x, wp[2 * q]);
            ffma2(acc2b, v.y, wp[2 * q + 1]);
        }
        float2 sa = unpk(acc2a), sb = unpk(acc2b);
        float acc = bias + axs[p] * w0 + (sa.x + sa.y) + (sb.x + sb.y);
        float sg = 1.f / (1.f + __expf(-acc));
        if (n < 2048) {
            const int idx = (2 * n + jh) * NC + p * UNITS + u2;
            g_RS[idx] = sg * g_S[idx];
        } else {
            g_UG[(2 * (n - 2048) + jh) * NC + p * UNITS + u2] = sg;
        }
    }
}

// ---------------- gate 2: c = tanh(gc2); state = u*state + (1-u)*c ----------------
// One block per node, ALL 32 batches.
__global__ __launch_bounds__(128)
void gates2_kernel(const float* __restrict__ W2, const float* __restrict__ b2, int t) {
    __shared__ __align__(16) float arr[32][64];
    __shared__ float axs[32];
    const int j  = threadIdx.x;
    const int n  = blockIdx.x;           // real node
    const int u2 = j & 63, ph = j >> 6;
    const float w0 = W2[u2];
    unsigned long long wp[32];           // pairs (w[2q+1], w[2q+2])
#pragma unroll
    for (int q = 0; q < 32; ++q)
        wp[q] = pk2(W2[(2 * q + 1) * 64 + u2], W2[(2 * q + 2) * 64 + u2]);
    const float bias = b2[u2];

    const float* src = g_AR + n * NC;
    for (int idx = j; idx < 2048; idx += 128) ((float*)arr)[idx] = src[idx];
    if (j < 32) axs[j] = g_AX[n * TB + t * BATCH + j];
    __syncthreads();

    for (int pp = 0; pp < 16; ++pp) {
        const int p = pp * 2 + ph;
        unsigned long long acc2a = 0ull, acc2b = 0ull;
        const ulonglong2* ap = (const ulonglong2*)arr[p];
#pragma unroll
        for (int q = 0; q < 16; ++q) {
            ulonglong2 v = ap[q];
            ffma2(acc2a, v.x, wp[2 * q]);
            ffma2(acc2b, v.y, wp[2 * q + 1]);
        }
        float2 sa = unpk(acc2a), sb = unpk(acc2b);
        float acc = bias + axs[p] * w0 + (sa.x + sa.y) + (sb.x + sb.y);
        float c = tanhf(acc);
        const int idx = n * NC + p * UNITS + u2;
        const float ug = g_UG[idx];
        g_S[idx] = ug * g_S[idx] + (1.f - ug) * c;
    }
}

// ---------------- output head: out[b,p,n] = state[b,n,:] @ Wo + bo ----------------
__global__ __launch_bounds__(128)
void final_kernel(const float* __restrict__ Wo, const float* __restrict__ bo,
                  float* __restrict__ out) {
    __shared__ float srow[NC];
    __shared__ float wo[UNITS * PRELEN];
    __shared__ float bos[PRELEN];
    const int n = blockIdx.x, j = threadIdx.x;
    for (int idx = j; idx < NC; idx += 128) srow[idx] = g_S[n * NC + idx];
    for (int idx = j; idx < UNITS * PRELEN; idx += 128) wo[idx] = Wo[idx];
    if (j < PRELEN) bos[j] = bo[j];
    __syncthreads();
    for (int o = j; o < BATCH * PRELEN; o += 128) {
        int b = o / PRELEN, p = o - b * PRELEN;
        float acc = bos[p];
#pragma unroll
        for (int u = 0; u < UNITS; ++u) acc += srow[b * UNITS + u] * wo[u * PRELEN + p];
        out[b * (PRELEN * N_NODES) + p * N_NODES + n] = acc;
    }
}

// ---------------- launch ----------------
extern "C" void kernel_launch(void* const* d_in, const int* in_sizes, int n_in,
                              void* d_out, int out_size) {
    const float* A  = (const float*)d_in[0];
    const float* X  = (const float*)d_in[1];
    const float* st = (const float*)d_in[2];
    const float* W1 = (const float*)d_in[3];
    const float* b1 = (const float*)d_in[4];
    const float* W2 = (const float*)d_in[5];
    const float* b2 = (const float*)d_in[6];
    const float* Wo = (const float*)d_in[7];
    const float* bo = (const float*)d_in[8];
    float* out = (float*)d_out;
    (void)in_sizes; (void)n_in; (void)out_size;

    float *pAS, *pAR, *pAX, *pS, *pRS;
    char *pAq, *pSq, *pRq, *pXq;
    cudaGetSymbolAddress((void**)&pAS, g_AS);
    cudaGetSymbolAddress((void**)&pAR, g_AR);
    cudaGetSymbolAddress((void**)&pAX, g_AX);
    cudaGetSymbolAddress((void**)&pS,  g_S);
    cudaGetSymbolAddress((void**)&pRS, g_RS);
    cudaGetSymbolAddress((void**)&pAq, g_Aq);
    cudaGetSymbolAddress((void**)&pSq, g_Sq);
    cudaGetSymbolAddress((void**)&pRq, g_Rq);
    cudaGetSymbolAddress((void**)&pXq, g_Xq);

    const int DSM = 3 * (int)STGB;   // 92160 B (x2 CTAs/SM = 184320 < 228KB)
    cudaFuncSetAttribute(imma_gemm, cudaFuncAttributeMaxDynamicSharedMemorySize, DSM);

    // one-time: quantize A and X; pack initial state
    quantA_kernel<<<(N_NODES * N_NODES + 255) / 256, 256>>>(A);
    quantX_kernel<<<(TB * N_NODES + 255) / 256, 256>>>(X);
    pack_s_kernel<<<(BATCH * N_NODES * UNITS + 255) / 256, 256>>>(st);

    // AX = A_hat @ X^T for all timesteps (6x32 = 192 CTAs -> single wave)
    imma_gemm<<<dim3(TB / 64, N_NODES / 128), 256, DSM>>>(pAX, pAq, pXq, TB,
                                                          (size_t)TB * N_NODES);

    for (int t = 0; t < TSTEPS; ++t) {
        quantT_kernel<<<dim3(NC / 32, N_NODES / 32), 256>>>(pS, pSq);
        imma_gemm<<<dim3(NC / 64, N_NODES / 128), 256, DSM>>>(pAS, pAq, pSq, NC,
                                                              (size_t)NC * N_NODES);
        gates1_kernel<<<N_NODES, 128>>>(W1, b1, t);
        quantT_kernel<<<dim3(NC / 32, N_NODES / 32), 256>>>(pRS, pRq);
        imma_gemm<<<dim3(NC / 64, N_NODES / 128), 256, DSM>>>(pAR, pAq, pRq, NC,
                                                              (size_t)NC * N_NODES);
        gates2_kernel<<<N_NODES, 128>>>(W2, b2, t);
    }

    final_kernel<<<N_NODES, 128>>>(Wo, bo, out);
}

// round 17
// speedup vs baseline: 1.0913x; 1.0513x over previous
#include <cuda_runtime.h>
#include <cstdint>

// ---------------- problem constants ----------------
#define N_NODES 4096
#define UNITS   64
#define BATCH   32
#define TSTEPS  12
#define PRELEN  12
#define NC      2048                 // GEMM columns for state (b*64+u)
#define TB      384                  // t*32+b columns for X
#define A_PART  ((size_t)N_NODES * N_NODES)
#define ROWB    80u                  // smem row stride: 64B data + 16B pad
#define NKT     (N_NODES/64)         // 64 k-tiles of BK=64

// ---------------- scratch (device globals; no allocation allowed) ----------------
__device__ __align__(128) float g_S [N_NODES*NC];   // state fp32 [node][col]
__device__ __align__(128) float g_AS[N_NODES*NC];   // A @ S
__device__ __align__(128) float g_RS[N_NODES*NC];   // r * state
__device__ __align__(128) float g_AR[N_NODES*NC];   // A @ RS
__device__ __align__(128) float g_AX[N_NODES*TB];   // A @ X (all steps)
__device__ __align__(128) char g_Aq[2*A_PART];                // A planes: a1 | a0, [m][k]
__device__ __align__(128) char g_Sq[2*(size_t)NC*N_NODES];    // S planes: b1 | b0, [n][k]
__device__ __align__(128) char g_Rq[2*(size_t)NC*N_NODES];    // RS planes
__device__ __align__(128) char g_Xq[2*(size_t)TB*N_NODES];    // X planes

// ---------------- PTX helpers (baseline PTX, sm_80+) ----------------
__device__ __forceinline__ uint32_t s2u(const void* p) {
    uint32_t a;
    asm("{ .reg .u64 t; cvta.to.shared.u64 t, %1; cvt.u32.u64 %0, t; }" : "=r"(a) : "l"(p));
    return a;
}
__device__ __forceinline__ void cp16(uint32_t dst, const void* src) {
    asm volatile("cp.async.cg.shared.global [%0], [%1], 16;" :: "r"(dst), "l"(src) : "memory");
}
__device__ __forceinline__ void cp_commit() {
    asm volatile("cp.async.commit_group;" ::: "memory");
}
template<int N>
__device__ __forceinline__ void cp_wait() {
    asm volatile("cp.async.wait_group %0;" :: "n"(N) : "memory");
}
__device__ __forceinline__ void ldm_x4(uint32_t* r, uint32_t a) {
    asm volatile("ldmatrix.sync.aligned.m8n8.x4.shared.b16 {%0,%1,%2,%3}, [%4];"
                 : "=r"(r[0]), "=r"(r[1]), "=r"(r[2]), "=r"(r[3]) : "r"(a));
}
// int8 IMMA m16n8k32, s32 accum — uniform s8.s8 (a1 in [0,64] is s8-safe)
__device__ __forceinline__ void imma_s8s8(int* d, const uint32_t* a, const uint32_t* b) {
    asm volatile(
        "mma.sync.aligned.m16n8k32.row.col.s32.s8.s8.s32 "
        "{%0,%1,%2,%3}, {%4,%5,%6,%7}, {%8,%9}, {%0,%1,%2,%3};"
        : "+r"(d[0]), "+r"(d[1]), "+r"(d[2]), "+r"(d[3])
        : "r"(a[0]), "r"(a[1]), "r"(a[2]), "r"(a[3]), "r"(b[0]), "r"(b[1]));
}
// packed fp32x2 FMA (Blackwell FFMA2)
__device__ __forceinline__ void ffma2(unsigned long long &d,
                                      unsigned long long a,
                                      unsigned long long b) {
    asm("fma.rn.f32x2 %0, %1, %2, %0;" : "+l"(d) : "l"(a), "l"(b));
}
__device__ __forceinline__ unsigned long long pk2(float x, float y) {
    unsigned long long r;
    asm("mov.b64 %0, {%1, %2};" : "=l"(r)
        : "r"(__float_as_uint(x)), "r"(__float_as_uint(y)));
    return r;
}
__device__ __forceinline__ float2 unpk(unsigned long long v) {
    unsigned int lo, hi;
    asm("mov.b64 {%0, %1}, %2;" : "=r"(lo), "=r"(hi) : "l"(v));
    return make_float2(__uint_as_float(lo), __uint_as_float(hi));
}

// ---------------- IMMA fixed-point split-GEMM ----------------
// C[m,n] = sum_k A[m,k]*B[n,k]; A = (a1*256 + a0)*2^-26, B = (b1*256 + b0)*2^-12.
// C = (acc_hh*65536 + acc_x*256)*2^-38 (dropped a0*b0: centered, zero-mean).
// CTA tile 128x64, 256 threads (2 CTAs/SM), warp grid 4m x 2n, warp tile 32x32.
// BK=64, 3-stage cp.async pipeline.
#define A0_OFF 10240u
#define B1_OFF 20480u
#define B0_OFF 25600u
#define STGB   30720u

__global__ __launch_bounds__(256, 2)
void imma_gemm(float* __restrict__ C, const char* __restrict__ Aq,
               const char* __restrict__ Bq, int ncols, size_t bPart) {
    extern __shared__ __align__(128) char smem[];
    const uint32_t sm0 = s2u(smem);

    const int tid = threadIdx.x;
    const int lane = tid & 31, wid = tid >> 5;
    const int wm = wid & 3, wn = wid >> 2;          // 4m x 2n warps, 32x32 tiles
    const int m0 = blockIdx.y * 128;
    const int n0 = blockIdx.x * 64;

    int acc_hh[2][4][4], acc_x[2][4][4];
#pragma unroll
    for (int i = 0; i < 2; ++i)
#pragma unroll
        for (int j = 0; j < 4; ++j)
#pragma unroll
            for (int q = 0; q < 4; ++q) { acc_hh[i][j][q] = 0; acc_x[i][j][q] = 0; }

    auto load_stage = [&](int kt) {
        const uint32_t sb = sm0 + (uint32_t)(kt % 3) * STGB;
        const size_t k0 = (size_t)kt * 64;
#pragma unroll
        for (int it = 0; it < 6; ++it) {
            const int i = tid + it * 256;           // 0..1535 16B chunks
            const int chunk = i & 3;                // 4 chunks = 64B row
            const int row = i >> 2;                 // 0..383
            const char* src;
            uint32_t rel;
            if (row < 256) {                        // A planes: a1 rows 0-127, a0 128-255
                const int plane = row >> 7, m = row & 127;
                src = Aq + (size_t)plane * A_PART + (size_t)(m0 + m) * N_NODES + k0;
                rel = (uint32_t)plane * A0_OFF + (uint32_t)m * ROWB;
            } else {                                // B planes: b1 rows 256-319, b0 320-383
                const int r = row - 256;
                const int plane = r >> 6, n = r & 63;
                src = Bq + (size_t)plane * bPart + (size_t)(n0 + n) * N_NODES + k0;
                rel = B1_OFF + (uint32_t)plane * (B0_OFF - B1_OFF) + (uint32_t)n * ROWB;
            }
            cp16(sb + rel + (uint32_t)chunk * 16u, src + chunk * 16);
        }
        cp_commit();
    };

    load_stage(0);
    load_stage(1);

    const uint32_t aLane = (uint32_t)(lane & 15) * ROWB + (uint32_t)((lane >> 4) << 4);
    const uint32_t bLane = (uint32_t)(((lane >> 4) << 3) + (lane & 7)) * ROWB
                         + (uint32_t)(((lane >> 3) & 1) << 4);

#pragma unroll 1
    for (int kt = 0; kt < NKT; ++kt) {
        if (kt < NKT - 1) cp_wait<1>();
        else              cp_wait<0>();
        __syncthreads();
        if (kt + 2 < NKT) load_stage(kt + 2);

        const uint32_t sb = sm0 + (uint32_t)(kt % 3) * STGB;
        const uint32_t aBase1 = sb + (uint32_t)(wm * 32) * ROWB + aLane;
        const uint32_t bBase1 = sb + B1_OFF + (uint32_t)(wn * 32) * ROWB + bLane;

#pragma unroll
        for (int ks = 0; ks < 2; ++ks) {
            const uint32_t kb = (uint32_t)(ks * 32);        // 32 int8 = 32B
            uint32_t fb1[4][2], fb0[4][2];
#pragma unroll
            for (int nf2 = 0; nf2 < 2; ++nf2) {
                const uint32_t off = (uint32_t)(nf2 * 16) * ROWB + kb;
                uint32_t t1[4], t0[4];
                ldm_x4(t1, bBase1 + off);
                ldm_x4(t0, bBase1 + off + (B0_OFF - B1_OFF));
                fb1[2 * nf2][0] = t1[0]; fb1[2 * nf2][1] = t1[1];
                fb1[2 * nf2 + 1][0] = t1[2]; fb1[2 * nf2 + 1][1] = t1[3];
                fb0[2 * nf2][0] = t0[0]; fb0[2 * nf2][1] = t0[1];
                fb0[2 * nf2 + 1][0] = t0[2]; fb0[2 * nf2 + 1][1] = t0[3];
            }
#pragma unroll
            for (int mf = 0; mf < 2; ++mf) {
                const uint32_t aa = aBase1 + (uint32_t)(mf * 16) * ROWB + kb;
                uint32_t fa1[4], fa0[4];
                ldm_x4(fa1, aa);
                ldm_x4(fa0, aa + A0_OFF);
#pragma unroll
                for (int nf = 0; nf < 4; ++nf) imma_s8s8(acc_hh[mf][nf], fa1, fb1[nf]);
#pragma unroll
                for (int nf = 0; nf < 4; ++nf) imma_s8s8(acc_x[mf][nf], fa1, fb0[nf]);
#pragma unroll
                for (int nf = 0; nf < 4; ++nf) imma_s8s8(acc_x[mf][nf], fa0, fb1[nf]);
            }
        }
    }

    // epilogue: C = (hh*2^16 + cross*2^8) * 2^-38
    const float SC = 3.637978807091713e-12f;   // 2^-38
    const int grp = lane >> 2, tl = lane & 3;
#pragma unroll
    for (int mf = 0; mf < 2; ++mf) {
#pragma unroll
        for (int nf = 0; nf < 4; ++nf) {
            const int row = m0 + wm * 32 + mf * 16 + grp;
            const int col = n0 + wn * 32 + nf * 8 + tl * 2;
            float* p0 = C + (size_t)row * ncols + col;
            float* p1 = C + (size_t)(row + 8) * ncols + col;
            p0[0] = ((float)acc_hh[mf][nf][0] * 65536.f + (float)acc_x[mf][nf][0] * 256.f) * SC;
            p0[1] = ((float)acc_hh[mf][nf][1] * 65536.f + (float)acc_x[mf][nf][1] * 256.f) * SC;
            p1[0] = ((float)acc_hh[mf][nf][2] * 65536.f + (float)acc_x[mf][nf][2] * 256.f) * SC;
            p1[1] = ((float)acc_hh[mf][nf][3] * 65536.f + (float)acc_x[mf][nf][3] * 256.f) * SC;
        }
    }
}

// ---------------- quantize A (once): A in [0, 2^-12) -> 16-bit fixed, planes a1|a0 ----------------
__global__ void quantA_kernel(const float* __restrict__ in) {
    int i = blockIdx.x * blockDim.x + threadIdx.x;
    if (i < N_NODES * N_NODES) {
        int q = (int)rintf(in[i] * 67108864.f);    // 2^26, <= 16384
        int h = (q + 128) >> 8;                     // [0,64]
        g_Aq[i] = (char)h;
        g_Aq[A_PART + i] = (char)(q - (h << 8));    // [-128,127]
    }
}

// ---------------- quantize B helper ----------------
__device__ __forceinline__ void quantB(float v, char& b1, char& b0) {
    v = fminf(fmaxf(v, -7.93f), 7.93f);
    int q = (int)rintf(v * 4096.f);                 // 2^12, |q| <= 32481
    int h = (q + 128) >> 8;                          // [-126,127]
    b1 = (char)h;
    b0 = (char)(q - (h << 8));                       // [-128,127]
}

// ---------------- quantize X (already [tb][node] k-contiguous) ----------------
__global__ void quantX_kernel(const float* __restrict__ X) {
    int i = blockIdx.x * blockDim.x + threadIdx.x;
    if (i < TB * N_NODES) {
        char b1, b0;
        quantB(X[i], b1, b0);
        g_Xq[i] = b1;
        g_Xq[(size_t)TB * N_NODES + i] = b0;
    }
}

// ---------------- transpose + quantize: fp32 [node][col] -> int8 planes [col][node] ----------------
// Writes vectorized as char4 (4 nodes per store).
__global__ __launch_bounds__(256)
void quantT_kernel(const float* __restrict__ in, char* __restrict__ out) {
    __shared__ float tile[32][33];
    const int col0 = blockIdx.x * 32, node0 = blockIdx.y * 32;
    const int tx = threadIdx.x & 31, ty = threadIdx.x >> 5;   // 32 x 8
#pragma unroll
    for (int j = 0; j < 32; j += 8)
        tile[ty + j][tx] = in[(size_t)(node0 + ty + j) * NC + col0 + tx];
    __syncthreads();
    // 256 threads: col = tid>>3 (0..31), grp = tid&7 -> nodes 4grp..4grp+3
    const int col = threadIdx.x >> 3, grp = threadIdx.x & 7;
    char4 v1, v0;
    char b1, b0;
    quantB(tile[4 * grp + 0][col], b1, b0); v1.x = b1; v0.x = b0;
    quantB(tile[4 * grp + 1][col], b1, b0); v1.y = b1; v0.y = b0;
    quantB(tile[4 * grp + 2][col], b1, b0); v1.z = b1; v0.z = b0;
    quantB(tile[4 * grp + 3][col], b1, b0); v1.w = b1; v0.w = b0;
    const size_t o = (size_t)(col0 + col) * N_NODES + node0 + 4 * grp;
    *(char4*)(out + o) = v1;
    *(char4*)(out + (size_t)NC * N_NODES + o) = v0;
}

// ---------------- input packing: state -> [node][col] fp32 ----------------
__global__ void pack_s_kernel(const float* __restrict__ st) {
    int i = blockIdx.x * blockDim.x + threadIdx.x;  // over B*N*U
    if (i < BATCH * N_NODES * UNITS) {
        int u = i & 63;
        int n = (i >> 6) & (N_NODES - 1);
        int b = i >> 18;
        g_S[n * NC + b * UNITS + u] = st[i];
    }
}

// ---------------- gate 1: r gates only -> RS (grid = 2048 v1-nodes) ----------------
// TGCN chunk(2,dim=1) quirk on flattened (N,2U):
//   v1[b,n,j] is r for node 2n+(j>>6), unit j&63   when n < 2048
// (The u half, v1-nodes >= 2048, is recomputed inside gates2 instead.)
__global__ __launch_bounds__(128)
void gates1_kernel(const float* __restrict__ W1, const float* __restrict__ b1, int t) {
    __shared__ __align__(16) float asr[32][64];
    __shared__ float axs[32];
    const int j  = threadIdx.x;          // 0..127 output feature
    const int n  = blockIdx.x;           // v1 node, 0..2047
    const float w0 = W1[j];
    unsigned long long wp[32];           // pairs (w[2q+1], w[2q+2])
#pragma unroll
    for (int q = 0; q < 32; ++q)
        wp[q] = pk2(W1[(2 * q + 1) * 128 + j], W1[(2 * q + 2) * 128 + j]);
    const float bias = b1[j];

    const float* src = g_AS + n * NC;
    for (int idx = j; idx < 2048; idx += 128) ((float*)asr)[idx] = src[idx];
    if (j < 32) axs[j] = g_AX[n * TB + t * BATCH + j];
    __syncthreads();

    const int jh = j >> 6, u2 = j & 63;
    for (int p = 0; p < 32; ++p) {
        unsigned long long acc2a = 0ull, acc2b = 0ull;
        const ulonglong2* ap = (const ulonglong2*)asr[p];
#pragma unroll
        for (int q = 0; q < 16; ++q) {
            ulonglong2 v = ap[q];
            ffma2(acc2a, v.x, wp[2 * q]);
            ffma2(acc2b, v.y, wp[2 * q + 1]);
        }
        float2 sa = unpk(acc2a), sb = unpk(acc2b);
        float acc = bias + axs[p] * w0 + (sa.x + sa.y) + (sb.x + sb.y);
        float sg = 1.f / (1.f + __expf(-acc));
        const int idx = (2 * n + jh) * NC + p * UNITS + u2;
        g_RS[idx] = sg * g_S[idx];
    }
}

// ---------------- gate 2: u recompute + c + state update (grid = 4096 nodes) ----------------
// u[n,b,u2] = sigmoid(gc1 at v1-node 2048 + n/2, feature (n&1)*64 + u2) — identical
// FFMA2 operand order as gates1, so u values are bit-identical to the old UG path.
// Thread (u2,ph) computes exactly the p's it later consumes -> u kept in registers.
__global__ __launch_bounds__(128)
void gates2_kernel(const float* __restrict__ W1, const float* __restrict__ b1,
                   const float* __restrict__ W2, const float* __restrict__ b2, int t) {
    __shared__ __align__(16) float arr[32][64];   // AR row n
    __shared__ __align__(16) float asu[32][64];   // AS row v1n (u-gate input)
    __shared__ float axc[32], axu[32];
    const int j  = threadIdx.x;
    const int n  = blockIdx.x;            // real node
    const int u2 = j & 63, ph = j >> 6;
    const int v1n  = 2048 + (n >> 1);
    const int jcol = ((n & 1) << 6) + u2; // W1 column for this node's u gate

    const float* srcC = g_AR + n * NC;
    const float* srcU = g_AS + (size_t)v1n * NC;
    for (int idx = j; idx < 2048; idx += 128) {
        ((float*)arr)[idx] = srcC[idx];
        ((float*)asu)[idx] = srcU[idx];
    }
    if (j < 32) {
        axc[j] = g_AX[n * TB + t * BATCH + j];
        axu[j] = g_AX[(size_t)v1n * TB + t * BATCH + j];
    }
    __syncthreads();

    // ---- phase 1: recompute u gates (16 per thread, in registers) ----
    float ug_r[16];
    {
        const float w0u = W1[jcol];
        const float biasu = b1[jcol];
        unsigned long long wpu[32];
#pragma unroll
        for (int q = 0; q < 32; ++q)
            wpu[q] = pk2(W1[(2 * q + 1) * 128 + jcol], W1[(2 * q + 2) * 128 + jcol]);
#pragma unroll 4
        for (int pp = 0; pp < 16; ++pp) {
            const int p = pp * 2 + ph;
            unsigned long long acc2a = 0ull, acc2b = 0ull;
            const ulonglong2* ap = (const ulonglong2*)asu[p];
#pragma unroll
            for (int q = 0; q < 16; ++q) {
                ulonglong2 v = ap[q];
                ffma2(acc2a, v.x, wpu[2 * q]);
                ffma2(acc2b, v.y, wpu[2 * q + 1]);
            }
            float2 sa = unpk(acc2a), sb = unpk(acc2b);
            float acc = biasu + axu[p] * w0u + (sa.x + sa.y) + (sb.x + sb.y);
            ug_r[pp] = 1.f / (1.f + __expf(-acc));
        }
    }

    // ---- phase 2: c = tanh(gc2); state = u*state + (1-u)*c ----
    {
        const float w0 = W2[u2];
        const float bias = b2[u2];
        unsigned long long wp[32];
#pragma unroll
        for (int q = 0; q < 32; ++q)
            wp[q] = pk2(W2[(2 * q + 1) * 64 + u2], W2[(2 * q + 2) * 64 + u2]);
#pragma unroll 4
        for (int pp = 0; pp < 16; ++pp) {
            const int p = pp * 2 + ph;
            unsigned long long acc2a = 0ull, acc2b = 0ull;
            const ulonglong2* ap = (const ulonglong2*)arr[p];
#pragma unroll
            for (int q = 0; q < 16; ++q) {
                ulonglong2 v = ap[q];
                ffma2(acc2a, v.x, wp[2 * q]);
                ffma2(acc2b, v.y, wp[2 * q + 1]);
            }
            float2 sa = unpk(acc2a), sb = unpk(acc2b);
            float acc = bias + axc[p] * w0 + (sa.x + sa.y) + (sb.x + sb.y);
            float c = tanhf(acc);
            const int idx = n * NC + p * UNITS + u2;
            const float ug = ug_r[pp];
            g_S[idx] = ug * g_S[idx] + (1.f - ug) * c;
        }
    }
}

// ---------------- output head: out[b,p,n] = state[b,n,:] @ Wo + bo ----------------
__global__ __launch_bounds__(128)
void final_kernel(const float* __restrict__ Wo, const float* __restrict__ bo,
                  float* __restrict__ out) {
    __shared__ float srow[NC];
    __shared__ float wo[UNITS * PRELEN];
    __shared__ float bos[PRELEN];
    const int n = blockIdx.x, j = threadIdx.x;
    for (int idx = j; idx < NC; idx += 128) srow[idx] = g_S[n * NC + idx];
    for (int idx = j; idx < UNITS * PRELEN; idx += 128) wo[idx] = Wo[idx];
    if (j < PRELEN) bos[j] = bo[j];
    __syncthreads();
    for (int o = j; o < BATCH * PRELEN; o += 128) {
        int b = o / PRELEN, p = o - b * PRELEN;
        float acc = bos[p];
#pragma unroll
        for (int u = 0; u < UNITS; ++u) acc += srow[b * UNITS + u] * wo[u * PRELEN + p];
        out[b * (PRELEN * N_NODES) + p * N_NODES + n] = acc;
    }
}

// ---------------- launch ----------------
extern "C" void kernel_launch(void* const* d_in, const int* in_sizes, int n_in,
                              void* d_out, int out_size) {
    const float* A  = (const float*)d_in[0];
    const float* X  = (const float*)d_in[1];
    const float* st = (const float*)d_in[2];
    const float* W1 = (const float*)d_in[3];
    const float* b1 = (const float*)d_in[4];
    const float* W2 = (const float*)d_in[5];
    const float* b2 = (const float*)d_in[6];
    const float* Wo = (const float*)d_in[7];
    const float* bo = (const float*)d_in[8];
    float* out = (float*)d_out;
    (void)in_sizes; (void)n_in; (void)out_size;

    float *pAS, *pAR, *pAX, *pS, *pRS;
    char *pAq, *pSq, *pRq, *pXq;
    cudaGetSymbolAddress((void**)&pAS, g_AS);
    cudaGetSymbolAddress((void**)&pAR, g_AR);
    cudaGetSymbolAddress((void**)&pAX, g_AX);
    cudaGetSymbolAddress((void**)&pS,  g_S);
    cudaGetSymbolAddress((void**)&pRS, g_RS);
    cudaGetSymbolAddress((void**)&pAq, g_Aq);
    cudaGetSymbolAddress((void**)&pSq, g_Sq);
    cudaGetSymbolAddress((void**)&pRq, g_Rq);
    cudaGetSymbolAddress((void**)&pXq, g_Xq);

    const int DSM = 3 * (int)STGB;   // 92160 B (x2 CTAs/SM = 184320 < 228KB)
    cudaFuncSetAttribute(imma_gemm, cudaFuncAttributeMaxDynamicSharedMemorySize, DSM);

    // one-time: quantize A and X; pack initial state
    quantA_kernel<<<(N_NODES * N_NODES + 255) / 256, 256>>>(A);
    quantX_kernel<<<(TB * N_NODES + 255) / 256, 256>>>(X);
    pack_s_kernel<<<(BATCH * N_NODES * UNITS + 255) / 256, 256>>>(st);

    // AX = A_hat @ X^T for all timesteps (6x32 = 192 CTAs -> single wave)
    imma_gemm<<<dim3(TB / 64, N_NODES / 128), 256, DSM>>>(pAX, pAq, pXq, TB,
                                                          (size_t)TB * N_NODES);

    for (int t = 0; t < TSTEPS; ++t) {
        quantT_kernel<<<dim3(NC / 32, N_NODES / 32), 256>>>(pS, pSq);
        imma_gemm<<<dim3(NC / 64, N_NODES / 128), 256, DSM>>>(pAS, pAq, pSq, NC,
                                                              (size_t)NC * N_NODES);
        gates1_kernel<<<2048, 128>>>(W1, b1, t);
        quantT_kernel<<<dim3(NC / 32, N_NODES / 32), 256>>>(pRS, pRq);
        imma_gemm<<<dim3(NC / 64, N_NODES / 128), 256, DSM>>>(pAR, pAq, pRq, NC,
                                                              (size_t)NC * N_NODES);
        gates2_kernel<<<N_NODES, 128>>>(W1, b1, W2, b2, t);
    }

    final_kernel<<<N_NODES, 128>>>(Wo, bo, out);
}